// round 14
// baseline (speedup 1.0000x reference)
#include <cuda_runtime.h>
#include <cuda_fp16.h>
#include <math.h>

#define NN 100000
#define EE 1600000
#define HH 128
#define CC 40
#define BN_EPS 1e-5f
#define SCAN_BLK 1024
#define SCAN_NB ((NN + SCAN_BLK - 1) / SCAN_BLK)   // 98

// ---------------- scratch ----------------
__device__ __half g_h16[(size_t)NN * HH];     // fp16 hidden state (gather + self-loop)
__device__ float  g_agg[(size_t)NN * HH];
__device__ double g_stats[2 * HH];
__device__ float  g_scale[HH];
__device__ float  g_shift[HH];
__device__ int    g_degcnt[NN];
__device__ float  g_dinv[NN];
__device__ float  g_invdeg[NN];
__device__ int    g_rowptr[NN];
__device__ int    g_cursor[NN];
__device__ int    g_blksum[SCAN_NB];
__device__ int2   g_csr[EE];

// ---------------- helpers ----------------
__device__ __forceinline__ float4 bn_relu4(float4 v, float4 sc, float4 sh) {
    float4 r;
    r.x = fmaxf(fmaf(v.x, sc.x, sh.x), 0.f);
    r.y = fmaxf(fmaf(v.y, sc.y, sh.y), 0.f);
    r.z = fmaxf(fmaf(v.z, sc.z, sh.z), 0.f);
    r.w = fmaxf(fmaf(v.w, sc.w, sh.w), 0.f);
    return r;
}

__device__ __forceinline__ void fma4(float4& a, float s, float4 w) {
    a.x = fmaf(s, w.x, a.x);
    a.y = fmaf(s, w.y, a.y);
    a.z = fmaf(s, w.z, a.z);
    a.w = fmaf(s, w.w, a.w);
}

// acc[8] += w * (8 halves packed in uint4)
__device__ __forceinline__ void fma8_h(float* a, float w, uint4 v) {
    float2 f0 = __half22float2(*reinterpret_cast<__half2*>(&v.x));
    float2 f1 = __half22float2(*reinterpret_cast<__half2*>(&v.y));
    float2 f2 = __half22float2(*reinterpret_cast<__half2*>(&v.z));
    float2 f3 = __half22float2(*reinterpret_cast<__half2*>(&v.w));
    a[0] = fmaf(w, f0.x, a[0]);
    a[1] = fmaf(w, f0.y, a[1]);
    a[2] = fmaf(w, f1.x, a[2]);
    a[3] = fmaf(w, f1.y, a[3]);
    a[4] = fmaf(w, f2.x, a[4]);
    a[5] = fmaf(w, f2.y, a[5]);
    a[6] = fmaf(w, f3.x, a[6]);
    a[7] = fmaf(w, f3.y, a[7]);
}

// ---------------- degree ----------------
__global__ void deg_count_kernel(const int* __restrict__ dst) {
    int e = blockIdx.x * blockDim.x + threadIdx.x;
    if (e < EE) atomicAdd(&g_degcnt[dst[e]], 1);
}

// ---------------- scan1: block-local exclusive scan + degree finish ----------------
__global__ __launch_bounds__(SCAN_BLK) void scan1_kernel() {
    __shared__ int sm[SCAN_BLK];
    int i = blockIdx.x * SCAN_BLK + threadIdx.x;
    int v = (i < NN) ? g_degcnt[i] : 0;
    sm[threadIdx.x] = v;
    __syncthreads();
    for (int off = 1; off < SCAN_BLK; off <<= 1) {
        int t = (threadIdx.x >= off) ? sm[threadIdx.x - off] : 0;
        __syncthreads();
        sm[threadIdx.x] += t;
        __syncthreads();
    }
    if (i < NN) {
        g_rowptr[i] = sm[threadIdx.x] - v;
        float f = (float)(v + 1);
        g_dinv[i]   = rsqrtf(f);
        g_invdeg[i] = 1.0f / f;
    }
    if (threadIdx.x == SCAN_BLK - 1) g_blksum[blockIdx.x] = sm[SCAN_BLK - 1];
}

// ---------------- scan23: block-prefix + cursor init ----------------
__global__ __launch_bounds__(256) void scan23_kernel() {
    __shared__ int sm[256];
    int t = threadIdx.x;
    int v = (t < SCAN_NB) ? g_blksum[t] : 0;
    sm[t] = v;
    __syncthreads();
    for (int off = 1; off < 256; off <<= 1) {
        int u = (t >= off) ? sm[t - off] : 0;
        __syncthreads();
        sm[t] += u;
        __syncthreads();
    }
    int i = blockIdx.x * 256 + t;
    if (i < NN) {
        int b = i >> 10;
        int pref = sm[b] - g_blksum[b];
        int rp = g_rowptr[i] + pref;
        g_rowptr[i] = rp;
        g_cursor[i] = rp;
    }
}

// ---------------- CSR fill ----------------
__global__ void csr_fill_kernel(const int* __restrict__ src,
                                const int* __restrict__ dst) {
    int e = blockIdx.x * blockDim.x + threadIdx.x;
    if (e >= EE) return;
    int s = src[e], d = dst[e];
    int pos = atomicAdd(&g_cursor[d], 1);
    float w = g_dinv[s] * g_dinv[d];
    g_csr[pos] = make_int2(s, __float_as_int(w));
}

// ---------------- GEMM [n,128]@[128,128] -> fp16 out, fused BN+ReLU on input ----------------
template<bool BN>
__global__ __launch_bounds__(256) void gemm128_kernel(
    const float* __restrict__ X, const float* __restrict__ W,
    __half* __restrict__ Y16, int nrows)
{
    extern __shared__ float smem[];
    float4* Ws = (float4*)smem;               // [128][32] float4
    float4* Xs = (float4*)smem + HH * 32;     // [8][8][32] float4

    int tid  = threadIdx.x;
    int lane = tid & 31, warp = tid >> 5;

    const float4* W4 = (const float4*)W;
    for (int i = tid; i < HH * 32; i += 256) Ws[i] = W4[i];
    __syncthreads();

    float4 sc, sh;
    if (BN) { sc = ((const float4*)g_scale)[lane]; sh = ((const float4*)g_shift)[lane]; }

    int base = blockIdx.x * 64 + warp * 8;
    const float4* X4 = (const float4*)X;
    float4* Xw = Xs + warp * 8 * 32;

#pragma unroll
    for (int r = 0; r < 8; r++) {
        int row = base + r;
        float4 xv = make_float4(0.f, 0.f, 0.f, 0.f);
        if (row < nrows) xv = X4[(size_t)row * 32 + lane];
        if (BN) xv = bn_relu4(xv, sc, sh);
        Xw[r * 32 + lane] = xv;
    }
    __syncwarp();

    float4 acc[8];
#pragma unroll
    for (int r = 0; r < 8; r++) acc[r] = make_float4(0.f, 0.f, 0.f, 0.f);

#pragma unroll 4
    for (int k0 = 0; k0 < 32; k0++) {
        float4 w0 = Ws[(4 * k0 + 0) * 32 + lane];
        float4 w1 = Ws[(4 * k0 + 1) * 32 + lane];
        float4 w2 = Ws[(4 * k0 + 2) * 32 + lane];
        float4 w3 = Ws[(4 * k0 + 3) * 32 + lane];
#pragma unroll
        for (int r = 0; r < 8; r++) {
            float4 xv = Xw[r * 32 + k0];
            fma4(acc[r], xv.x, w0);
            fma4(acc[r], xv.y, w1);
            fma4(acc[r], xv.z, w2);
            fma4(acc[r], xv.w, w3);
        }
    }

#pragma unroll
    for (int r = 0; r < 8; r++) {
        int row = base + r;
        if (row < nrows) {
            __half2 p0 = __floats2half2_rn(acc[r].x, acc[r].y);
            __half2 p1 = __floats2half2_rn(acc[r].z, acc[r].w);
            uint2 u;
            u.x = *reinterpret_cast<unsigned*>(&p0);
            u.y = *reinterpret_cast<unsigned*>(&p1);
            ((uint2*)Y16)[(size_t)row * 32 + lane] = u;
        }
    }
}

// ---------------- GEMM [n,128]@[128,40] -> fp16 out, fused BN+ReLU ----------------
template<bool BN>
__global__ __launch_bounds__(256) void gemm40_kernel(
    const float* __restrict__ X, const float* __restrict__ W,
    __half* __restrict__ Y16, int nrows)
{
    extern __shared__ float smem[];
    float*  Ws = smem;
    float4* Xs = (float4*)(smem + HH * CC);

    int tid  = threadIdx.x;
    int lane = tid & 31, warp = tid >> 5;

    for (int i = tid; i < HH * CC; i += 256) Ws[i] = W[i];
    __syncthreads();

    float4 sc, sh;
    if (BN) { sc = ((const float4*)g_scale)[lane]; sh = ((const float4*)g_shift)[lane]; }

    int base = blockIdx.x * 64 + warp * 8;
    const float4* X4 = (const float4*)X;
    float4* Xw = Xs + warp * 8 * 32;

#pragma unroll
    for (int r = 0; r < 8; r++) {
        int row = base + r;
        float4 xv = make_float4(0.f, 0.f, 0.f, 0.f);
        if (row < nrows) xv = X4[(size_t)row * 32 + lane];
        if (BN) xv = bn_relu4(xv, sc, sh);
        Xw[r * 32 + lane] = xv;
    }
    __syncwarp();

    float acca[8], accb[8];
#pragma unroll
    for (int r = 0; r < 8; r++) { acca[r] = 0.f; accb[r] = 0.f; }

    bool two = (lane < 8);

#pragma unroll 4
    for (int k0 = 0; k0 < 32; k0++) {
        float wa[4], wb[4];
#pragma unroll
        for (int j = 0; j < 4; j++) {
            wa[j] = Ws[(4 * k0 + j) * CC + lane];
            wb[j] = two ? Ws[(4 * k0 + j) * CC + 32 + lane] : 0.f;
        }
#pragma unroll
        for (int r = 0; r < 8; r++) {
            float4 xv = Xw[r * 32 + k0];
            acca[r] = fmaf(xv.x, wa[0], acca[r]);
            acca[r] = fmaf(xv.y, wa[1], acca[r]);
            acca[r] = fmaf(xv.z, wa[2], acca[r]);
            acca[r] = fmaf(xv.w, wa[3], acca[r]);
            accb[r] = fmaf(xv.x, wb[0], accb[r]);
            accb[r] = fmaf(xv.y, wb[1], accb[r]);
            accb[r] = fmaf(xv.z, wb[2], accb[r]);
            accb[r] = fmaf(xv.w, wb[3], accb[r]);
        }
    }

#pragma unroll
    for (int r = 0; r < 8; r++) {
        int row = base + r;
        if (row < nrows) {
            Y16[(size_t)row * CC + lane] = __float2half_rn(acca[r]);
            if (two) Y16[(size_t)row * CC + 32 + lane] = __float2half_rn(accb[r]);
        }
    }
}

// ---------------- fused CSR aggregation: 2 edges/warp (half-warp per edge), LDG.128 gathers ----------------
// lane = (half, sub): half = lane>>4 picks the edge, sub = lane&15 picks the 8-col chunk.
__global__ __launch_bounds__(256) void aggregate128_kernel(
    const __half* __restrict__ h16, float* __restrict__ agg,
    const float* __restrict__ bias)
{
    __shared__ float ssum[8 * HH];
    __shared__ float ssq[8 * HH];

    int lane = threadIdx.x & 31;
    int warp = threadIdx.x >> 5;
    int half = lane >> 4;
    int sub  = lane & 15;
    int gw = blockIdx.x * 8 + warp;
    int nwarps = gridDim.x * 8;

    const uint4* h16v = (const uint4*)h16;   // 16B chunks; row = 16 chunks

    float ps[8], ps2[8];
#pragma unroll
    for (int j = 0; j < 8; j++) { ps[j] = 0.f; ps2[j] = 0.f; }

    float bb[8];
#pragma unroll
    for (int j = 0; j < 8; j++) bb[j] = bias[sub * 8 + j];

    for (int i = gw; i < NN; i += nwarps) {
        int start = g_rowptr[i];
        int deg   = g_degcnt[i];
        float acc[8];
#pragma unroll
        for (int j = 0; j < 8; j++) acc[j] = 0.f;

        int kend = start + (deg & ~1);
        int k = start;
        // 2 pairs (4 edges) per iteration: 2 LDG.128 in flight
        for (; k + 3 < kend; k += 4) {
            int2 pa = g_csr[k + half];
            int2 pb = g_csr[k + 2 + half];
            uint4 va = __ldg(h16v + (size_t)pa.x * 16 + sub);
            uint4 vb = __ldg(h16v + (size_t)pb.x * 16 + sub);
            fma8_h(acc, __int_as_float(pa.y), va);
            fma8_h(acc, __int_as_float(pb.y), vb);
        }
        for (; k < kend; k += 2) {
            int2 pa = g_csr[k + half];
            uint4 va = __ldg(h16v + (size_t)pa.x * 16 + sub);
            fma8_h(acc, __int_as_float(pa.y), va);
        }
        if (half == 0) {
            if (deg & 1) {
                int2 pa = g_csr[start + deg - 1];
                uint4 va = __ldg(h16v + (size_t)pa.x * 16 + sub);
                fma8_h(acc, __int_as_float(pa.y), va);
            }
            // self-loop
            uint4 vs = h16v[(size_t)i * 16 + sub];
            fma8_h(acc, g_invdeg[i], vs);
        }

        // combine the two half-warps
#pragma unroll
        for (int j = 0; j < 8; j++)
            acc[j] += __shfl_xor_sync(0xFFFFFFFFu, acc[j], 16);

        if (half == 0) {
#pragma unroll
            for (int j = 0; j < 8; j++) acc[j] += bb[j];
            float4 o0 = make_float4(acc[0], acc[1], acc[2], acc[3]);
            float4 o1 = make_float4(acc[4], acc[5], acc[6], acc[7]);
            ((float4*)agg)[(size_t)i * 32 + sub * 2]     = o0;
            ((float4*)agg)[(size_t)i * 32 + sub * 2 + 1] = o1;
#pragma unroll
            for (int j = 0; j < 8; j++) {
                ps[j]  += acc[j];
                ps2[j]  = fmaf(acc[j], acc[j], ps2[j]);
            }
        }
    }

    if (half == 0) {
        float* su = ssum + warp * HH + sub * 8;
        float* sq = ssq  + warp * HH + sub * 8;
#pragma unroll
        for (int j = 0; j < 8; j++) { su[j] = ps[j]; sq[j] = ps2[j]; }
    }
    __syncthreads();
    if (threadIdx.x < HH) {
        int j = threadIdx.x;
        float ts = 0.f, ts2 = 0.f;
#pragma unroll
        for (int w = 0; w < 8; w++) {
            ts  += ssum[w * HH + j];
            ts2 += ssq[w * HH + j];
        }
        atomicAdd(&g_stats[j],      (double)ts);
        atomicAdd(&g_stats[HH + j], (double)ts2);
    }
}

// stats -> scale/shift, then zero stats for next layer / next replay
__global__ void stats_final_kernel(const float* __restrict__ g,
                                   const float* __restrict__ be)
{
    int j = threadIdx.x;
    double mu  = g_stats[j] / (double)NN;
    double var = g_stats[HH + j] / (double)NN - mu * mu;
    float rs = rsqrtf((float)var + BN_EPS);
    float sc = g[j] * rs;
    g_scale[j] = sc;
    g_shift[j] = be[j] - (float)mu * sc;
    g_stats[j] = 0.0;
    g_stats[HH + j] = 0.0;
}

// ---------------- layer-3: fused fp16-gather aggregation + self-loop + bias + log_softmax ----------------
__global__ __launch_bounds__(256) void aggregate40_softmax_kernel(
    const __half* __restrict__ h316, const float* __restrict__ b3,
    float* __restrict__ out)
{
    int lane = threadIdx.x & 31;
    int warp = threadIdx.x >> 5;
    int gw = blockIdx.x * 8 + warp;
    if (gw >= NN) return;

    int start = g_rowptr[gw];
    int end   = start + g_degcnt[gw];
    bool act = (lane < 20);

    const unsigned* h16u = (const unsigned*)h316;

    float a0 = 0.f, a1 = 0.f;
    for (int k = start; k < end; k++) {
        int2 p = g_csr[k];
        float w = __int_as_float(p.y);
        if (act) {
            unsigned u0 = __ldg(h16u + (size_t)p.x * 20 + lane);
            float2 f0 = __half22float2(*reinterpret_cast<__half2*>(&u0));
            a0 = fmaf(w, f0.x, a0);
            a1 = fmaf(w, f0.y, a1);
        }
    }

    size_t rb = (size_t)gw * CC;
    float id = g_invdeg[gw];
    float v0 = -INFINITY, v1 = -INFINITY;
    if (act) {
        unsigned us = h16u[(size_t)gw * 20 + lane];
        float2 fs = __half22float2(*reinterpret_cast<__half2*>(&us));
        v0 = fmaf(id, fs.x, a0) + b3[2 * lane];
        v1 = fmaf(id, fs.y, a1) + b3[2 * lane + 1];
    }

    float m = fmaxf(v0, v1);
#pragma unroll
    for (int off = 16; off > 0; off >>= 1)
        m = fmaxf(m, __shfl_xor_sync(0xFFFFFFFFu, m, off));

    float s = act ? (expf(v0 - m) + expf(v1 - m)) : 0.f;
#pragma unroll
    for (int off = 16; off > 0; off >>= 1)
        s += __shfl_xor_sync(0xFFFFFFFFu, s, off);

    float lse = m + logf(s);
    if (act) {
        out[rb + 2 * lane]     = v0 - lse;
        out[rb + 2 * lane + 1] = v1 - lse;
    }
}

// ---------------- launch ----------------
extern "C" void kernel_launch(void* const* d_in, const int* in_sizes, int n_in,
                              void* d_out, int out_size)
{
    const float* x   = (const float*)d_in[0];
    const float* W1  = (const float*)d_in[1];
    const float* b1  = (const float*)d_in[2];
    const float* W2  = (const float*)d_in[3];
    const float* b2  = (const float*)d_in[4];
    const float* W3  = (const float*)d_in[5];
    const float* b3  = (const float*)d_in[6];
    const float* g1  = (const float*)d_in[7];
    const float* be1 = (const float*)d_in[8];
    const float* g2  = (const float*)d_in[9];
    const float* be2 = (const float*)d_in[10];
    const int*   ei  = (const int*)d_in[11];
    const int* src = ei;
    const int* dst = ei + EE;
    float* out = (float*)d_out;

    void* p;
    cudaGetSymbolAddress(&p, g_h16);
    __half* h16 = (__half*)p;
    cudaGetSymbolAddress(&p, g_agg);
    float* agg = (float*)p;
    cudaGetSymbolAddress(&p, g_degcnt);
    int* degcnt = (int*)p;

    const int SMEM128 = (HH * HH + 8 * 8 * HH) * 4;   // 96 KB
    const int SMEM40  = (HH * CC + 8 * 8 * HH) * 4;   // 52 KB
    cudaFuncSetAttribute(gemm128_kernel<false>, cudaFuncAttributeMaxDynamicSharedMemorySize, SMEM128);
    cudaFuncSetAttribute(gemm128_kernel<true>,  cudaFuncAttributeMaxDynamicSharedMemorySize, SMEM128);
    cudaFuncSetAttribute(gemm40_kernel<true>,   cudaFuncAttributeMaxDynamicSharedMemorySize, SMEM40);

    const int GEMM_GRID = (NN + 63) / 64;
    const int AGG_GRID  = 1184;

    // ---- degree + CSR build ----
    cudaMemsetAsync(degcnt, 0, NN * sizeof(int));
    deg_count_kernel<<<(EE + 255) / 256, 256>>>(dst);
    scan1_kernel<<<SCAN_NB, SCAN_BLK>>>();
    scan23_kernel<<<(NN + 255) / 256, 256>>>();
    csr_fill_kernel<<<(EE + 255) / 256, 256>>>(src, dst);

    // ---- layer 1 ----
    gemm128_kernel<false><<<GEMM_GRID, 256, SMEM128>>>(x, W1, h16, NN);
    aggregate128_kernel<<<AGG_GRID, 256>>>(h16, agg, b1);
    stats_final_kernel<<<1, HH>>>(g1, be1);

    // ---- layer 2 ----
    gemm128_kernel<true><<<GEMM_GRID, 256, SMEM128>>>(agg, W2, h16, NN);
    aggregate128_kernel<<<AGG_GRID, 256>>>(h16, agg, b2);
    stats_final_kernel<<<1, HH>>>(g2, be2);

    // ---- layer 3 ----
    gemm40_kernel<true><<<GEMM_GRID, 256, SMEM40>>>(agg, W3, h16, NN);
    aggregate40_softmax_kernel<<<(NN + 7) / 8, 256>>>(h16, b3, out);
}

// round 15
// speedup vs baseline: 1.0409x; 1.0409x over previous
#include <cuda_runtime.h>
#include <cuda_fp16.h>
#include <math.h>

#define NN 100000
#define EE 1600000
#define HH 128
#define CC 40
#define BN_EPS 1e-5f
#define SCAN_BLK 1024
#define SCAN_NB ((NN + SCAN_BLK - 1) / SCAN_BLK)   // 98

// ---------------- scratch ----------------
__device__ __half g_h16[(size_t)NN * HH];     // fp16 hidden state (gather + self-loop)
__device__ __half g_agg16[(size_t)NN * HH];   // fp16 aggregation output (next-layer input)
__device__ double g_stats[2 * HH];
__device__ float  g_scale[HH];
__device__ float  g_shift[HH];
__device__ int    g_degcnt[NN];
__device__ float  g_dinv[NN];
__device__ float  g_invdeg[NN];
__device__ int    g_rowptr[NN];
__device__ int    g_cursor[NN];
__device__ int    g_blksum[SCAN_NB];
__device__ int2   g_csr[EE];

// ---------------- helpers ----------------
__device__ __forceinline__ float4 bn_relu4(float4 v, float4 sc, float4 sh) {
    float4 r;
    r.x = fmaxf(fmaf(v.x, sc.x, sh.x), 0.f);
    r.y = fmaxf(fmaf(v.y, sc.y, sh.y), 0.f);
    r.z = fmaxf(fmaf(v.z, sc.z, sh.z), 0.f);
    r.w = fmaxf(fmaf(v.w, sc.w, sh.w), 0.f);
    return r;
}

__device__ __forceinline__ void fma4(float4& a, float s, float4 w) {
    a.x = fmaf(s, w.x, a.x);
    a.y = fmaf(s, w.y, a.y);
    a.z = fmaf(s, w.z, a.z);
    a.w = fmaf(s, w.w, a.w);
}

// acc += w * (4 halves packed in uint2)
__device__ __forceinline__ void fma4_h(float4& a, float w, uint2 v) {
    __half2 h01 = *reinterpret_cast<__half2*>(&v.x);
    __half2 h23 = *reinterpret_cast<__half2*>(&v.y);
    float2 f01 = __half22float2(h01);
    float2 f23 = __half22float2(h23);
    a.x = fmaf(w, f01.x, a.x);
    a.y = fmaf(w, f01.y, a.y);
    a.z = fmaf(w, f23.x, a.z);
    a.w = fmaf(w, f23.y, a.w);
}

__device__ __forceinline__ float4 h4_to_f4(uint2 v) {
    float2 f01 = __half22float2(*reinterpret_cast<__half2*>(&v.x));
    float2 f23 = __half22float2(*reinterpret_cast<__half2*>(&v.y));
    return make_float4(f01.x, f01.y, f23.x, f23.y);
}

__device__ __forceinline__ uint2 f4_to_h4(float4 v) {
    __half2 p0 = __floats2half2_rn(v.x, v.y);
    __half2 p1 = __floats2half2_rn(v.z, v.w);
    uint2 u;
    u.x = *reinterpret_cast<unsigned*>(&p0);
    u.y = *reinterpret_cast<unsigned*>(&p1);
    return u;
}

// ---------------- degree ----------------
__global__ void deg_count_kernel(const int* __restrict__ dst) {
    int e = blockIdx.x * blockDim.x + threadIdx.x;
    if (e < EE) atomicAdd(&g_degcnt[dst[e]], 1);
}

// ---------------- scan1: block-local exclusive scan + degree finish ----------------
__global__ __launch_bounds__(SCAN_BLK) void scan1_kernel() {
    __shared__ int sm[SCAN_BLK];
    int i = blockIdx.x * SCAN_BLK + threadIdx.x;
    int v = (i < NN) ? g_degcnt[i] : 0;
    sm[threadIdx.x] = v;
    __syncthreads();
    for (int off = 1; off < SCAN_BLK; off <<= 1) {
        int t = (threadIdx.x >= off) ? sm[threadIdx.x - off] : 0;
        __syncthreads();
        sm[threadIdx.x] += t;
        __syncthreads();
    }
    if (i < NN) {
        g_rowptr[i] = sm[threadIdx.x] - v;
        float f = (float)(v + 1);
        g_dinv[i]   = rsqrtf(f);
        g_invdeg[i] = 1.0f / f;
    }
    if (threadIdx.x == SCAN_BLK - 1) g_blksum[blockIdx.x] = sm[SCAN_BLK - 1];
}

// ---------------- scan23: block-prefix + cursor init ----------------
__global__ __launch_bounds__(256) void scan23_kernel() {
    __shared__ int sm[256];
    int t = threadIdx.x;
    int v = (t < SCAN_NB) ? g_blksum[t] : 0;
    sm[t] = v;
    __syncthreads();
    for (int off = 1; off < 256; off <<= 1) {
        int u = (t >= off) ? sm[t - off] : 0;
        __syncthreads();
        sm[t] += u;
        __syncthreads();
    }
    int i = blockIdx.x * 256 + t;
    if (i < NN) {
        int b = i >> 10;
        int pref = sm[b] - g_blksum[b];
        int rp = g_rowptr[i] + pref;
        g_rowptr[i] = rp;
        g_cursor[i] = rp;
    }
}

// ---------------- CSR fill ----------------
__global__ void csr_fill_kernel(const int* __restrict__ src,
                                const int* __restrict__ dst) {
    int e = blockIdx.x * blockDim.x + threadIdx.x;
    if (e >= EE) return;
    int s = src[e], d = dst[e];
    int pos = atomicAdd(&g_cursor[d], 1);
    float w = g_dinv[s] * g_dinv[d];
    g_csr[pos] = make_int2(s, __float_as_int(w));
}

// ---------------- GEMM [n,128]@[128,128] -> fp16 out ----------------
// HALF_IN=false: fp32 input, no BN (layer 1). HALF_IN=true: fp16 input + BN+ReLU (layer 2).
template<bool HALF_IN>
__global__ __launch_bounds__(256) void gemm128_kernel(
    const void* __restrict__ Xv, const float* __restrict__ W,
    __half* __restrict__ Y16, int nrows)
{
    extern __shared__ float smem[];
    float4* Ws = (float4*)smem;               // [128][32] float4
    float4* Xs = (float4*)smem + HH * 32;     // [8][8][32] float4

    int tid  = threadIdx.x;
    int lane = tid & 31, warp = tid >> 5;

    const float4* W4 = (const float4*)W;
    for (int i = tid; i < HH * 32; i += 256) Ws[i] = W4[i];
    __syncthreads();

    float4 sc, sh;
    if (HALF_IN) { sc = ((const float4*)g_scale)[lane]; sh = ((const float4*)g_shift)[lane]; }

    int base = blockIdx.x * 64 + warp * 8;
    float4* Xw = Xs + warp * 8 * 32;

#pragma unroll
    for (int r = 0; r < 8; r++) {
        int row = base + r;
        float4 xv = make_float4(0.f, 0.f, 0.f, 0.f);
        if (row < nrows) {
            if (HALF_IN) {
                uint2 u = ((const uint2*)Xv)[(size_t)row * 32 + lane];
                xv = bn_relu4(h4_to_f4(u), sc, sh);
            } else {
                xv = ((const float4*)Xv)[(size_t)row * 32 + lane];
            }
        }
        Xw[r * 32 + lane] = xv;
    }
    __syncwarp();

    float4 acc[8];
#pragma unroll
    for (int r = 0; r < 8; r++) acc[r] = make_float4(0.f, 0.f, 0.f, 0.f);

#pragma unroll 4
    for (int k0 = 0; k0 < 32; k0++) {
        float4 w0 = Ws[(4 * k0 + 0) * 32 + lane];
        float4 w1 = Ws[(4 * k0 + 1) * 32 + lane];
        float4 w2 = Ws[(4 * k0 + 2) * 32 + lane];
        float4 w3 = Ws[(4 * k0 + 3) * 32 + lane];
#pragma unroll
        for (int r = 0; r < 8; r++) {
            float4 xv = Xw[r * 32 + k0];
            fma4(acc[r], xv.x, w0);
            fma4(acc[r], xv.y, w1);
            fma4(acc[r], xv.z, w2);
            fma4(acc[r], xv.w, w3);
        }
    }

#pragma unroll
    for (int r = 0; r < 8; r++) {
        int row = base + r;
        if (row < nrows)
            ((uint2*)Y16)[(size_t)row * 32 + lane] = f4_to_h4(acc[r]);
    }
}

// ---------------- GEMM [n,128]@[128,40] (fp16 input + BN+ReLU) -> fp16 out ----------------
__global__ __launch_bounds__(256) void gemm40_kernel(
    const __half* __restrict__ X16, const float* __restrict__ W,
    __half* __restrict__ Y16, int nrows)
{
    extern __shared__ float smem[];
    float*  Ws = smem;
    float4* Xs = (float4*)(smem + HH * CC);

    int tid  = threadIdx.x;
    int lane = tid & 31, warp = tid >> 5;

    for (int i = tid; i < HH * CC; i += 256) Ws[i] = W[i];
    __syncthreads();

    float4 sc = ((const float4*)g_scale)[lane];
    float4 sh = ((const float4*)g_shift)[lane];

    int base = blockIdx.x * 64 + warp * 8;
    float4* Xw = Xs + warp * 8 * 32;

#pragma unroll
    for (int r = 0; r < 8; r++) {
        int row = base + r;
        float4 xv = make_float4(0.f, 0.f, 0.f, 0.f);
        if (row < nrows) {
            uint2 u = ((const uint2*)X16)[(size_t)row * 32 + lane];
            xv = bn_relu4(h4_to_f4(u), sc, sh);
        }
        Xw[r * 32 + lane] = xv;
    }
    __syncwarp();

    float acca[8], accb[8];
#pragma unroll
    for (int r = 0; r < 8; r++) { acca[r] = 0.f; accb[r] = 0.f; }

    bool two = (lane < 8);

#pragma unroll 4
    for (int k0 = 0; k0 < 32; k0++) {
        float wa[4], wb[4];
#pragma unroll
        for (int j = 0; j < 4; j++) {
            wa[j] = Ws[(4 * k0 + j) * CC + lane];
            wb[j] = two ? Ws[(4 * k0 + j) * CC + 32 + lane] : 0.f;
        }
#pragma unroll
        for (int r = 0; r < 8; r++) {
            float4 xv = Xw[r * 32 + k0];
            acca[r] = fmaf(xv.x, wa[0], acca[r]);
            acca[r] = fmaf(xv.y, wa[1], acca[r]);
            acca[r] = fmaf(xv.z, wa[2], acca[r]);
            acca[r] = fmaf(xv.w, wa[3], acca[r]);
            accb[r] = fmaf(xv.x, wb[0], accb[r]);
            accb[r] = fmaf(xv.y, wb[1], accb[r]);
            accb[r] = fmaf(xv.z, wb[2], accb[r]);
            accb[r] = fmaf(xv.w, wb[3], accb[r]);
        }
    }

#pragma unroll
    for (int r = 0; r < 8; r++) {
        int row = base + r;
        if (row < nrows) {
            Y16[(size_t)row * CC + lane] = __float2half_rn(acca[r]);
            if (two) Y16[(size_t)row * CC + 32 + lane] = __float2half_rn(accb[r]);
        }
    }
}

// ---------------- fused CSR aggregation (fp16 gather, unroll-2) + self-loop + bias + BN stats ----------------
// writes agg as fp16; BN stats computed from fp32 accumulator
__global__ __launch_bounds__(256) void aggregate128_kernel(
    const __half* __restrict__ h16, __half* __restrict__ agg16,
    const float* __restrict__ bias)
{
    __shared__ float ssum[8 * HH];
    __shared__ float ssq[8 * HH];

    int lane = threadIdx.x & 31;
    int warp = threadIdx.x >> 5;
    int gw = blockIdx.x * 8 + warp;
    int nwarps = gridDim.x * 8;

    float4 bb = ((const float4*)bias)[lane];
    float4 ps  = make_float4(0.f, 0.f, 0.f, 0.f);
    float4 ps2 = make_float4(0.f, 0.f, 0.f, 0.f);

    const uint2* h16v = (const uint2*)h16;

    for (int i = gw; i < NN; i += nwarps) {
        int start = g_rowptr[i];
        int end   = start + g_degcnt[i];
        float4 acc = make_float4(0.f, 0.f, 0.f, 0.f);

        int k = start;
        for (; k + 1 < end; k += 2) {
            int2 p0 = g_csr[k];
            int2 p1 = g_csr[k + 1];
            uint2 v0 = __ldg(h16v + (size_t)p0.x * 32 + lane);
            uint2 v1 = __ldg(h16v + (size_t)p1.x * 32 + lane);
            fma4_h(acc, __int_as_float(p0.y), v0);
            fma4_h(acc, __int_as_float(p1.y), v1);
        }
        if (k < end) {
            int2 p0 = g_csr[k];
            uint2 v0 = __ldg(h16v + (size_t)p0.x * 32 + lane);
            fma4_h(acc, __int_as_float(p0.y), v0);
        }

        // self-loop from fp16 state + bias
        uint2 hv = h16v[(size_t)i * 32 + lane];
        fma4_h(acc, g_invdeg[i], hv);
        acc.x += bb.x;
        acc.y += bb.y;
        acc.z += bb.z;
        acc.w += bb.w;
        ((uint2*)agg16)[(size_t)i * 32 + lane] = f4_to_h4(acc);

        ps.x += acc.x;
        ps.y += acc.y;
        ps.z += acc.z;
        ps.w += acc.w;
        ps2.x = fmaf(acc.x, acc.x, ps2.x);
        ps2.y = fmaf(acc.y, acc.y, ps2.y);
        ps2.z = fmaf(acc.z, acc.z, ps2.z);
        ps2.w = fmaf(acc.w, acc.w, ps2.w);
    }

    ((float4*)(ssum + warp * HH))[lane] = ps;
    ((float4*)(ssq  + warp * HH))[lane] = ps2;
    __syncthreads();
    if (threadIdx.x < HH) {
        int j = threadIdx.x;
        float ts = 0.f, ts2 = 0.f;
#pragma unroll
        for (int w = 0; w < 8; w++) {
            ts  += ssum[w * HH + j];
            ts2 += ssq[w * HH + j];
        }
        atomicAdd(&g_stats[j],      (double)ts);
        atomicAdd(&g_stats[HH + j], (double)ts2);
    }
}

// stats -> scale/shift, then zero stats for next layer / next replay
__global__ void stats_final_kernel(const float* __restrict__ g,
                                   const float* __restrict__ be)
{
    int j = threadIdx.x;
    double mu  = g_stats[j] / (double)NN;
    double var = g_stats[HH + j] / (double)NN - mu * mu;
    float rs = rsqrtf((float)var + BN_EPS);
    float sc = g[j] * rs;
    g_scale[j] = sc;
    g_shift[j] = be[j] - (float)mu * sc;
    g_stats[j] = 0.0;
    g_stats[HH + j] = 0.0;
}

// ---------------- layer-3: fused fp16-gather aggregation + self-loop + bias + log_softmax ----------------
__global__ __launch_bounds__(256) void aggregate40_softmax_kernel(
    const __half* __restrict__ h316, const float* __restrict__ b3,
    float* __restrict__ out)
{
    int lane = threadIdx.x & 31;
    int warp = threadIdx.x >> 5;
    int gw = blockIdx.x * 8 + warp;
    if (gw >= NN) return;

    int start = g_rowptr[gw];
    int end   = start + g_degcnt[gw];
    bool act = (lane < 20);

    const unsigned* h16u = (const unsigned*)h316;

    float a0 = 0.f, a1 = 0.f;
    for (int k = start; k < end; k++) {
        int2 p = g_csr[k];
        float w = __int_as_float(p.y);
        if (act) {
            unsigned u0 = __ldg(h16u + (size_t)p.x * 20 + lane);
            float2 f0 = __half22float2(*reinterpret_cast<__half2*>(&u0));
            a0 = fmaf(w, f0.x, a0);
            a1 = fmaf(w, f0.y, a1);
        }
    }

    size_t rb = (size_t)gw * CC;
    float id = g_invdeg[gw];
    float v0 = -INFINITY, v1 = -INFINITY;
    if (act) {
        unsigned us = h16u[(size_t)gw * 20 + lane];
        float2 fs = __half22float2(*reinterpret_cast<__half2*>(&us));
        v0 = fmaf(id, fs.x, a0) + b3[2 * lane];
        v1 = fmaf(id, fs.y, a1) + b3[2 * lane + 1];
    }

    float m = fmaxf(v0, v1);
#pragma unroll
    for (int off = 16; off > 0; off >>= 1)
        m = fmaxf(m, __shfl_xor_sync(0xFFFFFFFFu, m, off));

    float s = act ? (expf(v0 - m) + expf(v1 - m)) : 0.f;
#pragma unroll
    for (int off = 16; off > 0; off >>= 1)
        s += __shfl_xor_sync(0xFFFFFFFFu, s, off);

    float lse = m + logf(s);
    if (act) {
        out[rb + 2 * lane]     = v0 - lse;
        out[rb + 2 * lane + 1] = v1 - lse;
    }
}

// ---------------- launch ----------------
extern "C" void kernel_launch(void* const* d_in, const int* in_sizes, int n_in,
                              void* d_out, int out_size)
{
    const float* x   = (const float*)d_in[0];
    const float* W1  = (const float*)d_in[1];
    const float* b1  = (const float*)d_in[2];
    const float* W2  = (const float*)d_in[3];
    const float* b2  = (const float*)d_in[4];
    const float* W3  = (const float*)d_in[5];
    const float* b3  = (const float*)d_in[6];
    const float* g1  = (const float*)d_in[7];
    const float* be1 = (const float*)d_in[8];
    const float* g2  = (const float*)d_in[9];
    const float* be2 = (const float*)d_in[10];
    const int*   ei  = (const int*)d_in[11];
    const int* src = ei;
    const int* dst = ei + EE;
    float* out = (float*)d_out;

    void* p;
    cudaGetSymbolAddress(&p, g_h16);
    __half* h16 = (__half*)p;
    cudaGetSymbolAddress(&p, g_agg16);
    __half* agg16 = (__half*)p;
    cudaGetSymbolAddress(&p, g_degcnt);
    int* degcnt = (int*)p;

    const int SMEM128 = (HH * HH + 8 * 8 * HH) * 4;   // 96 KB
    const int SMEM40  = (HH * CC + 8 * 8 * HH) * 4;   // 52 KB
    cudaFuncSetAttribute(gemm128_kernel<false>, cudaFuncAttributeMaxDynamicSharedMemorySize, SMEM128);
    cudaFuncSetAttribute(gemm128_kernel<true>,  cudaFuncAttributeMaxDynamicSharedMemorySize, SMEM128);
    cudaFuncSetAttribute(gemm40_kernel,         cudaFuncAttributeMaxDynamicSharedMemorySize, SMEM40);

    const int GEMM_GRID = (NN + 63) / 64;
    const int AGG_GRID  = 1184;

    // ---- degree + CSR build ----
    cudaMemsetAsync(degcnt, 0, NN * sizeof(int));
    deg_count_kernel<<<(EE + 255) / 256, 256>>>(dst);
    scan1_kernel<<<SCAN_NB, SCAN_BLK>>>();
    scan23_kernel<<<(NN + 255) / 256, 256>>>();
    csr_fill_kernel<<<(EE + 255) / 256, 256>>>(src, dst);

    // ---- layer 1 ----
    gemm128_kernel<false><<<GEMM_GRID, 256, SMEM128>>>(x, W1, h16, NN);
    aggregate128_kernel<<<AGG_GRID, 256>>>(h16, agg16, b1);
    stats_final_kernel<<<1, HH>>>(g1, be1);

    // ---- layer 2 ----
    gemm128_kernel<true><<<GEMM_GRID, 256, SMEM128>>>(agg16, W2, h16, NN);
    aggregate128_kernel<<<AGG_GRID, 256>>>(h16, agg16, b2);
    stats_final_kernel<<<1, HH>>>(g2, be2);

    // ---- layer 3 ----
    gemm40_kernel<<<GEMM_GRID, 256, SMEM40>>>(agg16, W3, h16, NN);
    aggregate40_softmax_kernel<<<(NN + 7) / 8, 256>>>(h16, b3, out);
}

// round 17
// speedup vs baseline: 1.2863x; 1.2357x over previous
#include <cuda_runtime.h>
#include <cuda_fp16.h>
#include <math.h>

#define NN 100000
#define EE 1600000
#define HH 128
#define CC 40
#define BN_EPS 1e-5f
#define SCAN_BLK 1024
#define SCAN_NB ((NN + SCAN_BLK - 1) / SCAN_BLK)   // 98
#define LDP 136                                    // padded smem row stride (halves)

// ---------------- scratch ----------------
__device__ __half g_h16[(size_t)NN * HH];     // fp16 hidden state (gather + self-loop)
__device__ __half g_agg16[(size_t)NN * HH];   // fp16 aggregation output (next-layer input)
__device__ double g_stats[2 * HH];
__device__ float  g_scale[HH];
__device__ float  g_shift[HH];
__device__ int    g_degcnt[NN];
__device__ float  g_dinv[NN];
__device__ float  g_invdeg[NN];
__device__ int    g_rowptr[NN];
__device__ int    g_cursor[NN];
__device__ int    g_blksum[SCAN_NB];
__device__ int2   g_csr[EE];

// ---------------- helpers ----------------
__device__ __forceinline__ float4 bn_relu4(float4 v, float4 sc, float4 sh) {
    float4 r;
    r.x = fmaxf(fmaf(v.x, sc.x, sh.x), 0.f);
    r.y = fmaxf(fmaf(v.y, sc.y, sh.y), 0.f);
    r.z = fmaxf(fmaf(v.z, sc.z, sh.z), 0.f);
    r.w = fmaxf(fmaf(v.w, sc.w, sh.w), 0.f);
    return r;
}

__device__ __forceinline__ void fma4_h(float4& a, float w, uint2 v) {
    __half2 h01 = *reinterpret_cast<__half2*>(&v.x);
    __half2 h23 = *reinterpret_cast<__half2*>(&v.y);
    float2 f01 = __half22float2(h01);
    float2 f23 = __half22float2(h23);
    a.x = fmaf(w, f01.x, a.x);
    a.y = fmaf(w, f01.y, a.y);
    a.z = fmaf(w, f23.x, a.z);
    a.w = fmaf(w, f23.y, a.w);
}

__device__ __forceinline__ float4 h4_to_f4(uint2 v) {
    float2 f01 = __half22float2(*reinterpret_cast<__half2*>(&v.x));
    float2 f23 = __half22float2(*reinterpret_cast<__half2*>(&v.y));
    return make_float4(f01.x, f01.y, f23.x, f23.y);
}

__device__ __forceinline__ uint2 f4_to_h4(float4 v) {
    __half2 p0 = __floats2half2_rn(v.x, v.y);
    __half2 p1 = __floats2half2_rn(v.z, v.w);
    uint2 u;
    u.x = *reinterpret_cast<unsigned*>(&p0);
    u.y = *reinterpret_cast<unsigned*>(&p1);
    return u;
}

__device__ __forceinline__ unsigned smem_u32(const void* p) {
    return (unsigned)__cvta_generic_to_shared(p);
}

__device__ __forceinline__ void ldmatrix_x4(unsigned* r, unsigned addr) {
    asm volatile("ldmatrix.sync.aligned.m8n8.x4.shared.b16 {%0,%1,%2,%3}, [%4];"
                 : "=r"(r[0]), "=r"(r[1]), "=r"(r[2]), "=r"(r[3]) : "r"(addr));
}

__device__ __forceinline__ void ldmatrix_x2_t(unsigned* r, unsigned addr) {
    asm volatile("ldmatrix.sync.aligned.m8n8.x2.trans.shared.b16 {%0,%1}, [%2];"
                 : "=r"(r[0]), "=r"(r[1]) : "r"(addr));
}

__device__ __forceinline__ void mma_f16(float* d, const unsigned* a, const unsigned* b) {
    asm volatile(
        "mma.sync.aligned.m16n8k16.row.col.f32.f16.f16.f32 "
        "{%0,%1,%2,%3}, {%4,%5,%6,%7}, {%8,%9}, {%0,%1,%2,%3};"
        : "+f"(d[0]), "+f"(d[1]), "+f"(d[2]), "+f"(d[3])
        : "r"(a[0]), "r"(a[1]), "r"(a[2]), "r"(a[3]), "r"(b[0]), "r"(b[1]));
}

// ---------------- degree ----------------
__global__ void deg_count_kernel(const int* __restrict__ dst) {
    int e = blockIdx.x * blockDim.x + threadIdx.x;
    if (e < EE) atomicAdd(&g_degcnt[dst[e]], 1);
}

// ---------------- scan1: block-local exclusive scan + degree finish ----------------
__global__ __launch_bounds__(SCAN_BLK) void scan1_kernel() {
    __shared__ int sm[SCAN_BLK];
    int i = blockIdx.x * SCAN_BLK + threadIdx.x;
    int v = (i < NN) ? g_degcnt[i] : 0;
    sm[threadIdx.x] = v;
    __syncthreads();
    for (int off = 1; off < SCAN_BLK; off <<= 1) {
        int t = (threadIdx.x >= off) ? sm[threadIdx.x - off] : 0;
        __syncthreads();
        sm[threadIdx.x] += t;
        __syncthreads();
    }
    if (i < NN) {
        g_rowptr[i] = sm[threadIdx.x] - v;
        float f = (float)(v + 1);
        g_dinv[i]   = rsqrtf(f);
        g_invdeg[i] = 1.0f / f;
    }
    if (threadIdx.x == SCAN_BLK - 1) g_blksum[blockIdx.x] = sm[SCAN_BLK - 1];
}

// ---------------- scan23: block-prefix + cursor init ----------------
__global__ __launch_bounds__(256) void scan23_kernel() {
    __shared__ int sm[256];
    int t = threadIdx.x;
    int v = (t < SCAN_NB) ? g_blksum[t] : 0;
    sm[t] = v;
    __syncthreads();
    for (int off = 1; off < 256; off <<= 1) {
        int u = (t >= off) ? sm[t - off] : 0;
        __syncthreads();
        sm[t] += u;
        __syncthreads();
    }
    int i = blockIdx.x * 256 + t;
    if (i < NN) {
        int b = i >> 10;
        int pref = sm[b] - g_blksum[b];
        int rp = g_rowptr[i] + pref;
        g_rowptr[i] = rp;
        g_cursor[i] = rp;
    }
}

// ---------------- CSR fill ----------------
__global__ void csr_fill_kernel(const int* __restrict__ src,
                                const int* __restrict__ dst) {
    int e = blockIdx.x * blockDim.x + threadIdx.x;
    if (e >= EE) return;
    int s = src[e], d = dst[e];
    int pos = atomicAdd(&g_cursor[d], 1);
    float w = g_dinv[s] * g_dinv[d];
    g_csr[pos] = make_int2(s, __float_as_int(w));
}

// ---------------- HMMA GEMM [n,128]@[128,128] fp16 operands, fp32 accum -> fp16 out ----------------
// 256 thr / 8 warps; block tile 128x128; warp tile 32x64. smem: Xh + Wh [128][LDP] halves each.
// HALF_IN=false: fp32 X, no BN (layer 1). HALF_IN=true: fp16 X + BN+ReLU (layer 2).
template<bool HALF_IN>
__global__ __launch_bounds__(256) void gemm128_mma_kernel(
    const void* __restrict__ Xv, const float* __restrict__ W,
    __half* __restrict__ Y16, int nrows)
{
    extern __shared__ __align__(16) char smraw[];
    __half* Xh = (__half*)smraw;
    __half* Wh = Xh + HH * LDP;

    int tid  = threadIdx.x;
    int lane = tid & 31;
    int warp = tid >> 5;

    // stage W [k][n] fp32 -> fp16
    for (int i = tid; i < HH * 32; i += 256) {
        int k = i >> 5;
        int n4 = i & 31;
        float4 wv = ((const float4*)W)[(size_t)k * 32 + n4];
        *(uint2*)(Wh + k * LDP + n4 * 4) = f4_to_h4(wv);
    }

    // stage X rows (BN+ReLU for layer 2)
    float4 sc, sh;
    int c4s = tid & 31;
    if (HALF_IN) {
        sc = ((const float4*)g_scale)[c4s];
        sh = ((const float4*)g_shift)[c4s];
    }
    int row0 = blockIdx.x * 128;
    for (int i = tid; i < 128 * 32; i += 256) {
        int r  = i >> 5;
        int c4 = i & 31;
        int row = row0 + r;
        uint2 u = make_uint2(0u, 0u);
        if (row < nrows) {
            if (HALF_IN) {
                uint2 xin = ((const uint2*)Xv)[(size_t)row * 32 + c4];
                u = f4_to_h4(bn_relu4(h4_to_f4(xin), sc, sh));
            } else {
                float4 xv = ((const float4*)Xv)[(size_t)row * 32 + c4];
                u = f4_to_h4(xv);
            }
        }
        *(uint2*)(Xh + r * LDP + c4 * 4) = u;
    }
    __syncthreads();

    int wm = (warp & 3) * 32;
    int wn = (warp >> 2) * 64;

    float acc[2][8][4];
#pragma unroll
    for (int mt = 0; mt < 2; mt++)
#pragma unroll
        for (int nt = 0; nt < 8; nt++)
#pragma unroll
            for (int j = 0; j < 4; j++) acc[mt][nt][j] = 0.f;

    int a_row = wm + (lane & 15);
    int a_col = (lane >> 4) << 3;
    int b_k   = (lane & 7) + (((lane >> 3) & 1) << 3);

    unsigned x_base = smem_u32(Xh);
    unsigned w_base = smem_u32(Wh);

#pragma unroll
    for (int k = 0; k < HH; k += 16) {
        unsigned Ah[2][4];
#pragma unroll
        for (int mt = 0; mt < 2; mt++) {
            unsigned off = (unsigned)((a_row + mt * 16) * LDP + k + a_col) * 2u;
            ldmatrix_x4(Ah[mt], x_base + off);
        }
#pragma unroll
        for (int nt = 0; nt < 8; nt++) {
            unsigned off = (unsigned)((k + b_k) * LDP + wn + nt * 8) * 2u;
            unsigned Bh[2];
            ldmatrix_x2_t(Bh, w_base + off);
            mma_f16(acc[0][nt], Ah[0], Bh);
            mma_f16(acc[1][nt], Ah[1], Bh);
        }
    }

    int tq = lane >> 2;
    int tr = lane & 3;
#pragma unroll
    for (int mt = 0; mt < 2; mt++) {
#pragma unroll
        for (int nt = 0; nt < 8; nt++) {
            int r0 = row0 + wm + mt * 16 + tq;
            int c  = wn + nt * 8 + tr * 2;
            if (r0 < nrows)
                *(__half2*)(Y16 + (size_t)r0 * HH + c) =
                    __floats2half2_rn(acc[mt][nt][0], acc[mt][nt][1]);
            if (r0 + 8 < nrows)
                *(__half2*)(Y16 + (size_t)(r0 + 8) * HH + c) =
                    __floats2half2_rn(acc[mt][nt][2], acc[mt][nt][3]);
        }
    }
}

// ---------------- GEMM [n,128]@[128,40] (fp16 input + BN+ReLU) -> fp16 out (SIMT) ----------------
__global__ __launch_bounds__(256) void gemm40_kernel(
    const __half* __restrict__ X16, const float* __restrict__ W,
    __half* __restrict__ Y16, int nrows)
{
    extern __shared__ float smem[];
    float*  Ws = smem;
    float4* Xs = (float4*)(smem + HH * CC);

    int tid  = threadIdx.x;
    int lane = tid & 31, warp = tid >> 5;

    for (int i = tid; i < HH * CC; i += 256) Ws[i] = W[i];
    __syncthreads();

    float4 sc = ((const float4*)g_scale)[lane];
    float4 sh = ((const float4*)g_shift)[lane];

    int base = blockIdx.x * 64 + warp * 8;
    float4* Xw = Xs + warp * 8 * 32;

#pragma unroll
    for (int r = 0; r < 8; r++) {
        int row = base + r;
        float4 xv = make_float4(0.f, 0.f, 0.f, 0.f);
        if (row < nrows) {
            uint2 u = ((const uint2*)X16)[(size_t)row * 32 + lane];
            xv = bn_relu4(h4_to_f4(u), sc, sh);
        }
        Xw[r * 32 + lane] = xv;
    }
    __syncwarp();

    float acca[8], accb[8];
#pragma unroll
    for (int r = 0; r < 8; r++) { acca[r] = 0.f; accb[r] = 0.f; }

    bool two = (lane < 8);

#pragma unroll 4
    for (int k0 = 0; k0 < 32; k0++) {
        float wa[4], wb[4];
#pragma unroll
        for (int j = 0; j < 4; j++) {
            wa[j] = Ws[(4 * k0 + j) * CC + lane];
            wb[j] = two ? Ws[(4 * k0 + j) * CC + 32 + lane] : 0.f;
        }
#pragma unroll
        for (int r = 0; r < 8; r++) {
            float4 xv = Xw[r * 32 + k0];
            acca[r] = fmaf(xv.x, wa[0], acca[r]);
            acca[r] = fmaf(xv.y, wa[1], acca[r]);
            acca[r] = fmaf(xv.z, wa[2], acca[r]);
            acca[r] = fmaf(xv.w, wa[3], acca[r]);
            accb[r] = fmaf(xv.x, wb[0], accb[r]);
            accb[r] = fmaf(xv.y, wb[1], accb[r]);
            accb[r] = fmaf(xv.z, wb[2], accb[r]);
            accb[r] = fmaf(xv.w, wb[3], accb[r]);
        }
    }

#pragma unroll
    for (int r = 0; r < 8; r++) {
        int row = base + r;
        if (row < nrows) {
            Y16[(size_t)row * CC + lane] = __float2half_rn(acca[r]);
            if (two) Y16[(size_t)row * CC + 32 + lane] = __float2half_rn(accb[r]);
        }
    }
}

// ---------------- fused CSR aggregation (fp16 gather, unroll-2) + self-loop + bias + BN stats ----------------
__global__ __launch_bounds__(256) void aggregate128_kernel(
    const __half* __restrict__ h16, __half* __restrict__ agg16,
    const float* __restrict__ bias)
{
    __shared__ float ssum[8 * HH];
    __shared__ float ssq[8 * HH];

    int lane = threadIdx.x & 31;
    int warp = threadIdx.x >> 5;
    int gw = blockIdx.x * 8 + warp;
    int nwarps = gridDim.x * 8;

    float4 bb = ((const float4*)bias)[lane];
    float4 ps  = make_float4(0.f, 0.f, 0.f, 0.f);
    float4 ps2 = make_float4(0.f, 0.f, 0.f, 0.f);

    const uint2* h16v = (const uint2*)h16;

    for (int i = gw; i < NN; i += nwarps) {
        int start = g_rowptr[i];
        int end   = start + g_degcnt[i];
        float4 acc = make_float4(0.f, 0.f, 0.f, 0.f);

        int k = start;
        for (; k + 1 < end; k += 2) {
            int2 p0 = g_csr[k];
            int2 p1 = g_csr[k + 1];
            uint2 v0 = __ldg(h16v + (size_t)p0.x * 32 + lane);
            uint2 v1 = __ldg(h16v + (size_t)p1.x * 32 + lane);
            fma4_h(acc, __int_as_float(p0.y), v0);
            fma4_h(acc, __int_as_float(p1.y), v1);
        }
        if (k < end) {
            int2 p0 = g_csr[k];
            uint2 v0 = __ldg(h16v + (size_t)p0.x * 32 + lane);
            fma4_h(acc, __int_as_float(p0.y), v0);
        }

        uint2 hv = h16v[(size_t)i * 32 + lane];
        fma4_h(acc, g_invdeg[i], hv);
        acc.x += bb.x;
        acc.y += bb.y;
        acc.z += bb.z;
        acc.w += bb.w;
        ((uint2*)agg16)[(size_t)i * 32 + lane] = f4_to_h4(acc);

        ps.x += acc.x;
        ps.y += acc.y;
        ps.z += acc.z;
        ps.w += acc.w;
        ps2.x = fmaf(acc.x, acc.x, ps2.x);
        ps2.y = fmaf(acc.y, acc.y, ps2.y);
        ps2.z = fmaf(acc.z, acc.z, ps2.z);
        ps2.w = fmaf(acc.w, acc.w, ps2.w);
    }

    ((float4*)(ssum + warp * HH))[lane] = ps;
    ((float4*)(ssq  + warp * HH))[lane] = ps2;
    __syncthreads();
    if (threadIdx.x < HH) {
        int j = threadIdx.x;
        float ts = 0.f, ts2 = 0.f;
#pragma unroll
        for (int w = 0; w < 8; w++) {
            ts  += ssum[w * HH + j];
            ts2 += ssq[w * HH + j];
        }
        atomicAdd(&g_stats[j],      (double)ts);
        atomicAdd(&g_stats[HH + j], (double)ts2);
    }
}

__global__ void stats_final_kernel(const float* __restrict__ g,
                                   const float* __restrict__ be)
{
    int j = threadIdx.x;
    double mu  = g_stats[j] / (double)NN;
    double var = g_stats[HH + j] / (double)NN - mu * mu;
    float rs = rsqrtf((float)var + BN_EPS);
    float sc = g[j] * rs;
    g_scale[j] = sc;
    g_shift[j] = be[j] - (float)mu * sc;
    g_stats[j] = 0.0;
    g_stats[HH + j] = 0.0;
}

// ---------------- layer-3: fused fp16-gather aggregation + self-loop + bias + log_softmax ----------------
__global__ __launch_bounds__(256) void aggregate40_softmax_kernel(
    const __half* __restrict__ h316, const float* __restrict__ b3,
    float* __restrict__ out)
{
    int lane = threadIdx.x & 31;
    int warp = threadIdx.x >> 5;
    int gw = blockIdx.x * 8 + warp;
    if (gw >= NN) return;

    int start = g_rowptr[gw];
    int end   = start + g_degcnt[gw];
    bool act = (lane < 20);

    const unsigned* h16u = (const unsigned*)h316;

    float a0 = 0.f, a1 = 0.f;
    for (int k = start; k < end; k++) {
        int2 p = g_csr[k];
        float w = __int_as_float(p.y);
        if (act) {
            unsigned u0 = __ldg(h16u + (size_t)p.x * 20 + lane);
            float2 f0 = __half22float2(*reinterpret_cast<__half2*>(&u0));
            a0 = fmaf(w, f0.x, a0);
            a1 = fmaf(w, f0.y, a1);
        }
    }

    size_t rb = (size_t)gw * CC;
    float id = g_invdeg[gw];
    float v0 = -INFINITY, v1 = -INFINITY;
    if (act) {
        unsigned us = h16u[(size_t)gw * 20 + lane];
        float2 fs = __half22float2(*reinterpret_cast<__half2*>(&us));
        v0 = fmaf(id, fs.x, a0) + b3[2 * lane];
        v1 = fmaf(id, fs.y, a1) + b3[2 * lane + 1];
    }

    float m = fmaxf(v0, v1);
#pragma unroll
    for (int off = 16; off > 0; off >>= 1)
        m = fmaxf(m, __shfl_xor_sync(0xFFFFFFFFu, m, off));

    float s = act ? (expf(v0 - m) + expf(v1 - m)) : 0.f;
#pragma unroll
    for (int off = 16; off > 0; off >>= 1)
        s += __shfl_xor_sync(0xFFFFFFFFu, s, off);

    float lse = m + logf(s);
    if (act) {
        out[rb + 2 * lane]     = v0 - lse;
        out[rb + 2 * lane + 1] = v1 - lse;
    }
}

// ---------------- launch ----------------
extern "C" void kernel_launch(void* const* d_in, const int* in_sizes, int n_in,
                              void* d_out, int out_size)
{
    const float* x   = (const float*)d_in[0];
    const float* W1  = (const float*)d_in[1];
    const float* b1  = (const float*)d_in[2];
    const float* W2  = (const float*)d_in[3];
    const float* b2  = (const float*)d_in[4];
    const float* W3  = (const float*)d_in[5];
    const float* b3  = (const float*)d_in[6];
    const float* g1  = (const float*)d_in[7];
    const float* be1 = (const float*)d_in[8];
    const float* g2  = (const float*)d_in[9];
    const float* be2 = (const float*)d_in[10];
    const int*   ei  = (const int*)d_in[11];
    const int* src = ei;
    const int* dst = ei + EE;
    float* out = (float*)d_out;

    void* p;
    cudaGetSymbolAddress(&p, g_h16);
    __half* h16 = (__half*)p;
    cudaGetSymbolAddress(&p, g_agg16);
    __half* agg16 = (__half*)p;
    cudaGetSymbolAddress(&p, g_degcnt);
    int* degcnt = (int*)p;

    const int SMEM_MMA = 2 * HH * LDP * 2;            // 69,632 B
    const int SMEM40   = (HH * CC + 8 * 8 * HH) * 4;  // 52 KB
    cudaFuncSetAttribute(gemm128_mma_kernel<false>, cudaFuncAttributeMaxDynamicSharedMemorySize, SMEM_MMA);
    cudaFuncSetAttribute(gemm128_mma_kernel<true>,  cudaFuncAttributeMaxDynamicSharedMemorySize, SMEM_MMA);
    cudaFuncSetAttribute(gemm40_kernel,             cudaFuncAttributeMaxDynamicSharedMemorySize, SMEM40);

    const int MMA_GRID = (NN + 127) / 128;   // 782
    const int G40_GRID = (NN + 63) / 64;
    const int AGG_GRID = 1184;

    // ---- degree + CSR build ----
    cudaMemsetAsync(degcnt, 0, NN * sizeof(int));
    deg_count_kernel<<<(EE + 255) / 256, 256>>>(dst);
    scan1_kernel<<<SCAN_NB, SCAN_BLK>>>();
    scan23_kernel<<<(NN + 255) / 256, 256>>>();
    csr_fill_kernel<<<(EE + 255) / 256, 256>>>(src, dst);

    // ---- layer 1 ----
    gemm128_mma_kernel<false><<<MMA_GRID, 256, SMEM_MMA>>>(x, W1, h16, NN);
    aggregate128_kernel<<<AGG_GRID, 256>>>(h16, agg16, b1);
    stats_final_kernel<<<1, HH>>>(g1, be1);

    // ---- layer 2 ----
    gemm128_mma_kernel<true><<<MMA_GRID, 256, SMEM_MMA>>>(agg16, W2, h16, NN);
    aggregate128_kernel<<<AGG_GRID, 256>>>(h16, agg16, b2);
    stats_final_kernel<<<1, HH>>>(g2, be2);

    // ---- layer 3 ----
    gemm40_kernel<<<G40_GRID, 256, SMEM40>>>(agg16, W3, h16, NN);
    aggregate40_softmax_kernel<<<(NN + 7) / 8, 256>>>(h16, b3, out);
}